// round 14
// baseline (speedup 1.0000x reference)
#include <cuda_runtime.h>
#include <stdint.h>

#define BB      4
#define NN      16384
#define NPOINT  2048
#define CC      64
#define NSAMPLE 32
#define GRID    10
#define NCELLS  1024        // 10*10*10 = 1000, padded (pad cells scan to total)
#define R2      0.01f
#define R2PRUNE 0.01001f
#define CAND_CAP 192
#define OUTC    (CC + 3)    // 67

#define HIST_BLOCKS 64                              // 64 x 256 x 4 points
#define SC_BLOCKS   64                              // 16 per batch
#define BQ_BLOCKS   ((BB * NPOINT) / 8)             // 1024 blocks, 8 warps each
#define TR_TILES    ((NN / 32) * (CC / 32) * BB)    // 4096 tiles

// scratch (static device globals; zero-initialized at module load).
// g_counts is re-zeroed inside bq blocks each run so replays start clean.
__device__ int    g_counts  [BB * NCELLS];
__device__ int    g_starts  [BB * NCELLS];         // exclusive scan; starts[c+1] = end of c
__device__ int    g_cellrank[BB * NN];             // (cell<<20)|rank
__device__ float4 g_pts  [BB * NN];                // cell-ordered {x,y,z,bitcast(pid)}
__device__ int    g_idx  [BB * NPOINT * NSAMPLE];  // plain pid per sample
__device__ float  g_ft   [BB * NN * CC];           // features transposed [B][N][C]

// ---------------------------------------------------------------- K1: histogram (+rank)
__global__ void __launch_bounds__(256) hist_kernel(const float* __restrict__ xyz)
{
    int t0 = blockIdx.x * 256 + threadIdx.x;
#pragma unroll
    for (int k = 0; k < 4; k++) {
        int i = t0 + k * (HIST_BLOCKS * 256);
        float x = xyz[i * 3 + 0];
        float y = xyz[i * 3 + 1];
        float z = xyz[i * 3 + 2];
        int cx = (int)(x * 10.0f); cx = cx < 0 ? 0 : (cx > GRID - 1 ? GRID - 1 : cx);
        int cy = (int)(y * 10.0f); cy = cy < 0 ? 0 : (cy > GRID - 1 ? GRID - 1 : cy);
        int cz = (int)(z * 10.0f); cz = cz < 0 ? 0 : (cz > GRID - 1 ? GRID - 1 : cz);
        int cell = (cz * GRID + cy) * GRID + cx;
        int b = i / NN;
        int rank = atomicAdd(&g_counts[b * NCELLS + cell], 1);
        g_cellrank[i] = (cell << 20) | rank;
    }
}

// ---------------------------------------------------------------- K2: scan (redundant per block) + scatter
__global__ void __launch_bounds__(256) scan_scatter_kernel(const float* __restrict__ xyz)
{
    __shared__ int starts_s[NCELLS];
    __shared__ int wsum[8];

    int bb = blockIdx.x;          // 0..63
    int b  = bb >> 4;             // batch
    int t  = threadIdx.x;
    int lane = t & 31, wid = t >> 5;

    int base = t * 4;
    const int* cnt = g_counts + b * NCELLS;
    int a0 = cnt[base + 0], a1 = cnt[base + 1], a2 = cnt[base + 2], a3 = cnt[base + 3];
    int s = a0 + a1 + a2 + a3;
    int incl = s;
#pragma unroll
    for (int o = 1; o < 32; o <<= 1) {
        int y = __shfl_up_sync(0xffffffffu, incl, o);
        if (lane >= o) incl += y;
    }
    if (lane == 31) wsum[wid] = incl;
    __syncthreads();
    if (wid == 0 && lane < 8) {
        int w = wsum[lane];
        int wi = w;
#pragma unroll
        for (int o = 1; o < 8; o <<= 1) {
            int y = __shfl_up_sync(0x000000ffu, wi, o);
            if (lane >= o) wi += y;
        }
        wsum[lane] = wi - w;
    }
    __syncthreads();
    int excl = incl - s + wsum[wid];
    starts_s[base + 0] = excl;
    starts_s[base + 1] = excl + a0;
    starts_s[base + 2] = excl + a0 + a1;
    starts_s[base + 3] = excl + a0 + a1 + a2;
    __syncthreads();

    if ((bb & 15) == 0) {
#pragma unroll
        for (int k = 0; k < 4; k++)
            g_starts[b * NCELLS + base + k] = starts_s[base + k];
    }

    int chunk = (bb & 15) * 1024;
#pragma unroll
    for (int k = 0; k < 4; k++) {
        int i = chunk + t + k * 256;
        int gi = b * NN + i;
        int cr = g_cellrank[gi];
        int cell = cr >> 20;
        int rank = cr & 0xfffff;
        int slot = starts_s[cell] + rank;
        const float* p = xyz + (size_t)gi * 3;
        g_pts[b * NN + slot] = make_float4(p[0], p[1], p[2], __int_as_float(i));
    }
}

// ---------------------------------------------------------------- register bitonic helpers
__device__ __forceinline__ int bsort32(int v, int lane) {
#pragma unroll
    for (int k = 2; k <= 32; k <<= 1) {
#pragma unroll
        for (int j = k >> 1; j > 0; j >>= 1) {
            int p = __shfl_xor_sync(0xffffffffu, v, j);
            bool keep_min = ((lane & j) == 0) == ((lane & k) == 0);
            v = keep_min ? min(v, p) : max(v, p);
        }
    }
    return v;   // ascending across lanes
}

// ---------------------------------------------------------------- K3: ball query (warp/query, writes xyz channels) ∥ transpose
__global__ void __launch_bounds__(256) bq_tr_kernel(
    const float* __restrict__ new_xyz, const float* __restrict__ feat,
    const float* __restrict__ xyz, float* __restrict__ out)
{
    if (blockIdx.x >= BQ_BLOCKS) {
        __shared__ float tile[32][33];
        int tb  = blockIdx.x - BQ_BLOCKS;
        int b   = tb / ((NN / 32) * (CC / 32));
        int rem = tb % ((NN / 32) * (CC / 32));
        int n0  = (rem % (NN / 32)) * 32;
        int c0  = (rem / (NN / 32)) * 32;
        int t   = threadIdx.x;

        int c  = t >> 3;          // 0..31
        int nq = t & 7;           // 0..7
        float4 v = *(const float4*)(feat + ((size_t)(b * CC + c0 + c)) * NN + n0 + 4 * nq);
        tile[4 * nq + 0][c] = v.x;
        tile[4 * nq + 1][c] = v.y;
        tile[4 * nq + 2][c] = v.z;
        tile[4 * nq + 3][c] = v.w;
        __syncthreads();

        int n  = t >> 3;
        int cq = t & 7;
        float4 w = make_float4(tile[n][4 * cq + 0], tile[n][4 * cq + 1],
                               tile[n][4 * cq + 2], tile[n][4 * cq + 3]);
        *(float4*)(g_ft + ((size_t)(b * NN + n0 + n)) * CC + c0 + 4 * cq) = w;
        return;
    }

    // re-zero g_counts for the next run (scan_scatter already consumed it)
    if (blockIdx.x < 16)
        g_counts[blockIdx.x * 256 + threadIdx.x] = 0;

    __shared__ int buf_s[8][CAND_CAP];
    int warp = threadIdx.x >> 5;
    int lane = threadIdx.x & 31;
    int qid  = blockIdx.x * 8 + warp;
    int b = qid / NPOINT;
    int p = qid % NPOINT;

    float qx = new_xyz[qid * 3 + 0];
    float qy = new_xyz[qid * 3 + 1];
    float qz = new_xyz[qid * 3 + 2];
    int cy = (int)(qy * 10.0f); cy = cy < 0 ? 0 : (cy > GRID - 1 ? GRID - 1 : cy);
    int cz = (int)(qz * 10.0f); cz = cz < 0 ? 0 : (cz > GRID - 1 ? GRID - 1 : cz);

    int* buf = buf_s[warp];
    int cnt = 0;

    int z0 = cz > 0 ? cz - 1 : 0, z1 = cz < GRID - 1 ? cz + 1 : GRID - 1;
    int y0 = cy > 0 ? cy - 1 : 0, y1 = cy < GRID - 1 ? cy + 1 : GRID - 1;

    const float4* pts = g_pts + b * NN;
    const int* starts = g_starts + b * NCELLS;

    for (int zc = z0; zc <= z1; zc++) {
        float dz = (zc < cz) ? (qz - (zc + 1) * 0.1f) : ((zc > cz) ? (zc * 0.1f - qz) : 0.0f);
        float dz2 = dz * dz;
        for (int yc = y0; yc <= y1; yc++) {
            float dy = (yc < cy) ? (qy - (yc + 1) * 0.1f) : ((yc > cy) ? (yc * 0.1f - qy) : 0.0f);
            float rem2 = R2PRUNE - dz2 - dy * dy;
            if (rem2 <= 0.0f) continue;
            float rx = sqrtf(rem2);
            int xlo = (int)((qx - rx) * 10.0f); xlo = xlo < 0 ? 0 : (xlo > GRID - 1 ? GRID - 1 : xlo);
            int xhi = (int)((qx + rx) * 10.0f); xhi = xhi < 0 ? 0 : (xhi > GRID - 1 ? GRID - 1 : xhi);
            int bse = (zc * GRID + yc) * GRID;
            int s0 = starts[bse + xlo];
            int e  = starts[bse + xhi + 1];
            int len = e - s0;
            for (int j0 = 0; j0 < len; j0 += 32) {
                int j = j0 + lane;
                bool valid = false;
                int packed = 0;
                if (j < len) {
                    float4 pt = pts[s0 + j];
                    float ddx = qx - pt.x;
                    float ddy = qy - pt.y;
                    float ddz = qz - pt.z;
                    valid = (ddx * ddx + ddy * ddy + ddz * ddz) < R2;
                    packed = (__float_as_int(pt.w) << 14) | (s0 + j);   // (pid<<14)|slot
                }
                unsigned m = __ballot_sync(0xffffffffu, valid);
                int off = __popc(m & ((1u << lane) - 1));
                if (valid && (cnt + off) < CAND_CAP) buf[cnt + off] = packed;
                cnt += __popc(m);
                if (cnt > CAND_CAP) cnt = CAND_CAP;
            }
        }
    }
    __syncwarp();

    // top-32 smallest packed (== smallest pid) via register bitonic sort+merge
    int res = (lane < cnt) ? buf[lane] : 0x7fffffff;
    res = bsort32(res, lane);
    int nchunks = (cnt + 31) >> 5;
    for (int c = 1; c < nchunks; c++) {
        int idx = c * 32 + lane;
        int v = (idx < cnt) ? buf[idx] : 0x7fffffff;
        v = bsort32(v, lane);
        int vr = __shfl_sync(0xffffffffu, v, 31 - lane);
        res = min(res, vr);
#pragma unroll
        for (int j = 16; j > 0; j >>= 1) {
            int pp = __shfl_xor_sync(0xffffffffu, res, j);
            res = ((lane & j) == 0) ? min(res, pp) : max(res, pp);
        }
    }
    int first = __shfl_sync(0xffffffffu, res, 0);
    int eff = (lane < cnt) ? res : first;

    float px, py, pz;
    int pid;
    if (cnt == 0) {
        pid = 0;
        px = xyz[(size_t)b * NN * 3 + 0];   // broadcast
        py = xyz[(size_t)b * NN * 3 + 1];
        pz = xyz[(size_t)b * NN * 3 + 2];
    } else {
        pid = eff >> 14;
        float4 pt = pts[eff & 0x3fff];      // clustered slots: few sectors
        px = pt.x; py = pt.y; pz = pt.z;
    }

    // xyz output channels: coalesced 128B stores
    size_t ob = (((size_t)b * OUTC) * NPOINT + p) * NSAMPLE + lane;
    out[ob]                                = px - qx;
    out[ob + (size_t)NPOINT * NSAMPLE]     = py - qy;
    out[ob + 2 * (size_t)NPOINT * NSAMPLE] = pz - qz;

    g_idx[qid * NSAMPLE + lane] = pid;
}

// ---------------------------------------------------------------- K4: grouping — warp owns a whole query, NO block barrier
__global__ void __launch_bounds__(256) group_kernel(float* __restrict__ out)
{
    __shared__ float T[8][NSAMPLE][OUTC];   // per-warp private 32x67 patch

    int t    = threadIdx.x;
    int lane = t & 31;
    int w    = t >> 5;                 // warp = query within block
    int qid  = blockIdx.x * 8 + w;
    int b = qid / NPOINT;
    int p = qid % NPOINT;

    // this warp's 32 sample pids: lane s holds pid of sample s
    int v = g_idx[qid * NSAMPLE + lane];

    float (*Tq)[OUTC] = T[w];

    // gather all 32 rows in chunks of 8 (MLP=8 per thread), stage to private patch
#pragma unroll
    for (int ch = 0; ch < 4; ch++) {
        int rows[8];
#pragma unroll
        for (int j = 0; j < 8; j++)
            rows[j] = __shfl_sync(0xffffffffu, v, ch * 8 + j);
        float2 vals[8];
#pragma unroll
        for (int j = 0; j < 8; j++)
            vals[j] = ((const float2*)(g_ft + ((size_t)(b * NN + rows[j])) * CC))[lane];
#pragma unroll
        for (int j = 0; j < 8; j++) {
            int s = ch * 8 + j;            // parity(s) == parity(j)
            if ((j & 1) == 0) {
                *(float2*)&Tq[s][2 * lane] = vals[j];   // row start 8B-aligned for even s
            } else {
                Tq[s][2 * lane + 0] = vals[j].x;
                Tq[s][2 * lane + 1] = vals[j].y;
            }
        }
    }
    __syncwarp();

    // output: 16 STG.128; each instr = 4 channels x 8 sample-quarters
    // = 4 contiguous 128B rows (fully coalesced). LDS banks conflict-free (stride 67).
    float4* out4 = (float4*)(out + (((size_t)b * OUTC + 3) * NPOINT + p) * NSAMPLE);
#pragma unroll
    for (int k = 0; k < 16; k++) {
        int f  = k * 32 + lane;
        int c  = f >> 3;
        int sq = f & 7;
        float4 wv;
        wv.x = Tq[4 * sq + 0][c];
        wv.y = Tq[4 * sq + 1][c];
        wv.z = Tq[4 * sq + 2][c];
        wv.w = Tq[4 * sq + 3][c];
        out4[(size_t)c * (NPOINT * NSAMPLE / 4) + sq] = wv;
    }
}

// ---------------------------------------------------------------- launch
extern "C" void kernel_launch(void* const* d_in, const int* in_sizes, int n_in,
                              void* d_out, int out_size)
{
    const float* xyz     = (const float*)d_in[0];
    const float* new_xyz = (const float*)d_in[1];
    const float* feat    = (const float*)d_in[2];
    float* out = (float*)d_out;

    hist_kernel<<<HIST_BLOCKS, 256>>>(xyz);
    scan_scatter_kernel<<<SC_BLOCKS, 256>>>(xyz);
    bq_tr_kernel<<<BQ_BLOCKS + TR_TILES, 256>>>(new_xyz, feat, xyz, out);
    group_kernel<<<BB * NPOINT / 8, 256>>>(out);
}

// round 15
// speedup vs baseline: 1.0056x; 1.0056x over previous
#include <cuda_runtime.h>
#include <stdint.h>

#define BB      4
#define NN      16384
#define NPOINT  2048
#define CC      64
#define NSAMPLE 32
#define GRID    10
#define NCELLS  1024        // 10*10*10 = 1000, padded (pad cells scan to total)
#define R2      0.01f
#define R2PRUNE 0.01001f
#define CAND_CAP 192
#define OUTC    (CC + 3)    // 67

#define HIST_BLOCKS 64                              // 64 x 256 x 4 points
#define SC_BLOCKS   64                              // 16 per batch
#define BQ_BLOCKS   ((BB * NPOINT) / 8)             // 1024 blocks, 8 warps each
#define TR_TILES    ((NN / 32) * (CC / 32) * BB)    // 4096 tiles
#define TR_K1       1365                            // tiles in hist launch
#define TR_K2       1365                            // tiles in scan_scatter launch
#define TR_K3       (TR_TILES - TR_K1 - TR_K2)      // tiles in bq launch

// scratch (static device globals; zero-initialized at module load).
// g_counts is re-zeroed inside bq blocks each run so replays start clean.
__device__ int    g_counts  [BB * NCELLS];
__device__ int    g_starts  [BB * NCELLS];         // exclusive scan; starts[c+1] = end of c
__device__ int    g_cellrank[BB * NN];             // (cell<<20)|rank
__device__ float4 g_pts  [BB * NN];                // cell-ordered {x,y,z,bitcast(pid)}
__device__ int    g_idx  [BB * NPOINT * NSAMPLE];  // plain pid per sample
__device__ float  g_ft   [BB * NN * CC];           // features transposed [B][N][C]

// ---------------------------------------------------------------- transpose one 32x32 tile of [B,C,N] -> [B,N,C]
__device__ __forceinline__ void tr_tile(int tb, const float* __restrict__ feat)
{
    __shared__ float tile[32][33];
    int b   = tb / ((NN / 32) * (CC / 32));
    int rem = tb % ((NN / 32) * (CC / 32));
    int n0  = (rem % (NN / 32)) * 32;
    int c0  = (rem / (NN / 32)) * 32;
    int t   = threadIdx.x;

    int c  = t >> 3;          // 0..31
    int nq = t & 7;           // 0..7
    float4 v = *(const float4*)(feat + ((size_t)(b * CC + c0 + c)) * NN + n0 + 4 * nq);
    tile[4 * nq + 0][c] = v.x;
    tile[4 * nq + 1][c] = v.y;
    tile[4 * nq + 2][c] = v.z;
    tile[4 * nq + 3][c] = v.w;
    __syncthreads();

    int n  = t >> 3;
    int cq = t & 7;
    float4 w = make_float4(tile[n][4 * cq + 0], tile[n][4 * cq + 1],
                           tile[n][4 * cq + 2], tile[n][4 * cq + 3]);
    *(float4*)(g_ft + ((size_t)(b * NN + n0 + n)) * CC + c0 + 4 * cq) = w;
}

// ---------------------------------------------------------------- K1: histogram (+rank) ∥ transpose part 1
__global__ void __launch_bounds__(256) hist_kernel(
    const float* __restrict__ xyz, const float* __restrict__ feat)
{
    if (blockIdx.x >= HIST_BLOCKS) {
        tr_tile(blockIdx.x - HIST_BLOCKS, feat);
        return;
    }
    int t0 = blockIdx.x * 256 + threadIdx.x;
#pragma unroll
    for (int k = 0; k < 4; k++) {
        int i = t0 + k * (HIST_BLOCKS * 256);
        float x = xyz[i * 3 + 0];
        float y = xyz[i * 3 + 1];
        float z = xyz[i * 3 + 2];
        int cx = (int)(x * 10.0f); cx = cx < 0 ? 0 : (cx > GRID - 1 ? GRID - 1 : cx);
        int cy = (int)(y * 10.0f); cy = cy < 0 ? 0 : (cy > GRID - 1 ? GRID - 1 : cy);
        int cz = (int)(z * 10.0f); cz = cz < 0 ? 0 : (cz > GRID - 1 ? GRID - 1 : cz);
        int cell = (cz * GRID + cy) * GRID + cx;
        int b = i / NN;
        int rank = atomicAdd(&g_counts[b * NCELLS + cell], 1);
        g_cellrank[i] = (cell << 20) | rank;
    }
}

// ---------------------------------------------------------------- K2: scan + scatter ∥ transpose part 2
__global__ void __launch_bounds__(256) scan_scatter_kernel(
    const float* __restrict__ xyz, const float* __restrict__ feat)
{
    if (blockIdx.x >= SC_BLOCKS) {
        tr_tile(TR_K1 + blockIdx.x - SC_BLOCKS, feat);
        return;
    }

    __shared__ int starts_s[NCELLS];
    __shared__ int wsum[8];

    int bb = blockIdx.x;          // 0..63
    int b  = bb >> 4;             // batch
    int t  = threadIdx.x;
    int lane = t & 31, wid = t >> 5;

    int base = t * 4;
    const int* cnt = g_counts + b * NCELLS;
    int a0 = cnt[base + 0], a1 = cnt[base + 1], a2 = cnt[base + 2], a3 = cnt[base + 3];
    int s = a0 + a1 + a2 + a3;
    int incl = s;
#pragma unroll
    for (int o = 1; o < 32; o <<= 1) {
        int y = __shfl_up_sync(0xffffffffu, incl, o);
        if (lane >= o) incl += y;
    }
    if (lane == 31) wsum[wid] = incl;
    __syncthreads();
    if (wid == 0 && lane < 8) {
        int w = wsum[lane];
        int wi = w;
#pragma unroll
        for (int o = 1; o < 8; o <<= 1) {
            int y = __shfl_up_sync(0x000000ffu, wi, o);
            if (lane >= o) wi += y;
        }
        wsum[lane] = wi - w;
    }
    __syncthreads();
    int excl = incl - s + wsum[wid];
    starts_s[base + 0] = excl;
    starts_s[base + 1] = excl + a0;
    starts_s[base + 2] = excl + a0 + a1;
    starts_s[base + 3] = excl + a0 + a1 + a2;
    __syncthreads();

    if ((bb & 15) == 0) {
#pragma unroll
        for (int k = 0; k < 4; k++)
            g_starts[b * NCELLS + base + k] = starts_s[base + k];
    }

    int chunk = (bb & 15) * 1024;
#pragma unroll
    for (int k = 0; k < 4; k++) {
        int i = chunk + t + k * 256;
        int gi = b * NN + i;
        int cr = g_cellrank[gi];
        int cell = cr >> 20;
        int rank = cr & 0xfffff;
        int slot = starts_s[cell] + rank;
        const float* p = xyz + (size_t)gi * 3;
        g_pts[b * NN + slot] = make_float4(p[0], p[1], p[2], __int_as_float(i));
    }
}

// ---------------------------------------------------------------- register bitonic helpers
__device__ __forceinline__ int bsort32(int v, int lane) {
#pragma unroll
    for (int k = 2; k <= 32; k <<= 1) {
#pragma unroll
        for (int j = k >> 1; j > 0; j >>= 1) {
            int p = __shfl_xor_sync(0xffffffffu, v, j);
            bool keep_min = ((lane & j) == 0) == ((lane & k) == 0);
            v = keep_min ? min(v, p) : max(v, p);
        }
    }
    return v;   // ascending across lanes
}

// ---------------------------------------------------------------- K3: ball query (warp/query, writes xyz channels) ∥ transpose part 3
__global__ void __launch_bounds__(256) bq_tr_kernel(
    const float* __restrict__ new_xyz, const float* __restrict__ feat,
    const float* __restrict__ xyz, float* __restrict__ out)
{
    if (blockIdx.x >= BQ_BLOCKS) {
        tr_tile(TR_K1 + TR_K2 + blockIdx.x - BQ_BLOCKS, feat);
        return;
    }

    // re-zero g_counts for the next run (scan_scatter already consumed it)
    if (blockIdx.x < 16)
        g_counts[blockIdx.x * 256 + threadIdx.x] = 0;

    __shared__ int buf_s[8][CAND_CAP];
    int warp = threadIdx.x >> 5;
    int lane = threadIdx.x & 31;
    int qid  = blockIdx.x * 8 + warp;
    int b = qid / NPOINT;
    int p = qid % NPOINT;

    float qx = new_xyz[qid * 3 + 0];
    float qy = new_xyz[qid * 3 + 1];
    float qz = new_xyz[qid * 3 + 2];
    int cy = (int)(qy * 10.0f); cy = cy < 0 ? 0 : (cy > GRID - 1 ? GRID - 1 : cy);
    int cz = (int)(qz * 10.0f); cz = cz < 0 ? 0 : (cz > GRID - 1 ? GRID - 1 : cz);

    int* buf = buf_s[warp];
    int cnt = 0;

    int z0 = cz > 0 ? cz - 1 : 0, z1 = cz < GRID - 1 ? cz + 1 : GRID - 1;
    int y0 = cy > 0 ? cy - 1 : 0, y1 = cy < GRID - 1 ? cy + 1 : GRID - 1;

    const float4* pts = g_pts + b * NN;
    const int* starts = g_starts + b * NCELLS;

    for (int zc = z0; zc <= z1; zc++) {
        float dz = (zc < cz) ? (qz - (zc + 1) * 0.1f) : ((zc > cz) ? (zc * 0.1f - qz) : 0.0f);
        float dz2 = dz * dz;
        for (int yc = y0; yc <= y1; yc++) {
            float dy = (yc < cy) ? (qy - (yc + 1) * 0.1f) : ((yc > cy) ? (yc * 0.1f - qy) : 0.0f);
            float rem2 = R2PRUNE - dz2 - dy * dy;
            if (rem2 <= 0.0f) continue;
            float rx = sqrtf(rem2);
            int xlo = (int)((qx - rx) * 10.0f); xlo = xlo < 0 ? 0 : (xlo > GRID - 1 ? GRID - 1 : xlo);
            int xhi = (int)((qx + rx) * 10.0f); xhi = xhi < 0 ? 0 : (xhi > GRID - 1 ? GRID - 1 : xhi);
            int bse = (zc * GRID + yc) * GRID;
            int s0 = starts[bse + xlo];
            int e  = starts[bse + xhi + 1];
            int len = e - s0;
            for (int j0 = 0; j0 < len; j0 += 32) {
                int j = j0 + lane;
                bool valid = false;
                int packed = 0;
                if (j < len) {
                    float4 pt = pts[s0 + j];
                    float ddx = qx - pt.x;
                    float ddy = qy - pt.y;
                    float ddz = qz - pt.z;
                    valid = (ddx * ddx + ddy * ddy + ddz * ddz) < R2;
                    packed = (__float_as_int(pt.w) << 14) | (s0 + j);   // (pid<<14)|slot
                }
                unsigned m = __ballot_sync(0xffffffffu, valid);
                int off = __popc(m & ((1u << lane) - 1));
                if (valid && (cnt + off) < CAND_CAP) buf[cnt + off] = packed;
                cnt += __popc(m);
                if (cnt > CAND_CAP) cnt = CAND_CAP;
            }
        }
    }
    __syncwarp();

    // top-32 smallest packed (== smallest pid) via register bitonic sort+merge
    int res = (lane < cnt) ? buf[lane] : 0x7fffffff;
    res = bsort32(res, lane);
    int nchunks = (cnt + 31) >> 5;
    for (int c = 1; c < nchunks; c++) {
        int idx = c * 32 + lane;
        int v = (idx < cnt) ? buf[idx] : 0x7fffffff;
        v = bsort32(v, lane);
        int vr = __shfl_sync(0xffffffffu, v, 31 - lane);
        res = min(res, vr);
#pragma unroll
        for (int j = 16; j > 0; j >>= 1) {
            int pp = __shfl_xor_sync(0xffffffffu, res, j);
            res = ((lane & j) == 0) ? min(res, pp) : max(res, pp);
        }
    }
    int first = __shfl_sync(0xffffffffu, res, 0);
    int eff = (lane < cnt) ? res : first;

    float px, py, pz;
    int pid;
    if (cnt == 0) {
        pid = 0;
        px = xyz[(size_t)b * NN * 3 + 0];   // broadcast
        py = xyz[(size_t)b * NN * 3 + 1];
        pz = xyz[(size_t)b * NN * 3 + 2];
    } else {
        pid = eff >> 14;
        float4 pt = pts[eff & 0x3fff];      // clustered slots: few sectors
        px = pt.x; py = pt.y; pz = pt.z;
    }

    // xyz output channels: coalesced 128B stores
    size_t ob = (((size_t)b * OUTC) * NPOINT + p) * NSAMPLE + lane;
    out[ob]                                = px - qx;
    out[ob + (size_t)NPOINT * NSAMPLE]     = py - qy;
    out[ob + 2 * (size_t)NPOINT * NSAMPLE] = pz - qz;

    g_idx[qid * NSAMPLE + lane] = pid;
}

// ---------------------------------------------------------------- K4: grouping (features only, 2 queries/block) — R13 verbatim
__global__ void __launch_bounds__(256) group_kernel(float* __restrict__ out)
{
    __shared__ __align__(16) float T[2][NSAMPLE][OUTC];   // stride 67

    int t    = threadIdx.x;
    int ql   = t >> 7;                 // 0/1: query within block
    int tl   = t & 127;
    int lane = t & 31;
    int w    = tl >> 5;                // warp within query 0..3
    int qid  = blockIdx.x * 2 + ql;
    int b = qid / NPOINT;
    int p = qid % NPOINT;

    // per-warp coalesced idx load; sample s pid lives in lane s
    int v = g_idx[qid * NSAMPLE + lane];

    // rows for this warp's samples (w*8..w*8+7) via shfl; batch loads for MLP
    int rows[8];
#pragma unroll
    for (int j = 0; j < 8; j++)
        rows[j] = __shfl_sync(0xffffffffu, v, w * 8 + j);
    float2 vals[8];
#pragma unroll
    for (int j = 0; j < 8; j++)
        vals[j] = ((const float2*)(g_ft + ((size_t)(b * NN + rows[j])) * CC))[lane];

#pragma unroll
    for (int j = 0; j < 8; j++) {
        int s = w * 8 + j;                 // parity(s) == parity(j)
        if ((j & 1) == 0) {
            *(float2*)&T[ql][s][2 * lane] = vals[j];
        } else {
            T[ql][s][2 * lane + 0] = vals[j].x;
            T[ql][s][2 * lane + 1] = vals[j].y;
        }
    }
    __syncthreads();

    // feature output: float4 along sample dim; per instr each warp covers
    // 4 channels x 8 sample-quarters = 4 contiguous 128B rows (fully coalesced)
    float4* out4 = (float4*)(out + (((size_t)b * OUTC + 3) * NPOINT + p) * NSAMPLE);
#pragma unroll
    for (int k = 0; k < 4; k++) {
        int f  = tl + 128 * k;
        int c  = f >> 3;
        int sq = f & 7;
        float4 wv;
        wv.x = T[ql][4 * sq + 0][c];
        wv.y = T[ql][4 * sq + 1][c];
        wv.z = T[ql][4 * sq + 2][c];
        wv.w = T[ql][4 * sq + 3][c];
        out4[(size_t)c * (NPOINT * NSAMPLE / 4) + sq] = wv;
    }
}

// ---------------------------------------------------------------- launch
extern "C" void kernel_launch(void* const* d_in, const int* in_sizes, int n_in,
                              void* d_out, int out_size)
{
    const float* xyz     = (const float*)d_in[0];
    const float* new_xyz = (const float*)d_in[1];
    const float* feat    = (const float*)d_in[2];
    float* out = (float*)d_out;

    hist_kernel<<<HIST_BLOCKS + TR_K1, 256>>>(xyz, feat);
    scan_scatter_kernel<<<SC_BLOCKS + TR_K2, 256>>>(xyz, feat);
    bq_tr_kernel<<<BQ_BLOCKS + TR_K3, 256>>>(new_xyz, feat, xyz, out);
    group_kernel<<<BB * NPOINT / 2, 256>>>(out);
}

// round 16
// speedup vs baseline: 1.0990x; 1.0929x over previous
#include <cuda_runtime.h>
#include <stdint.h>

#define BB      4
#define NN      16384
#define NPOINT  2048
#define CC      64
#define NSAMPLE 32
#define GRID    10
#define NCELLS  1024        // 10*10*10 = 1000, padded (pad cells scan to total)
#define R2      0.01f
#define R2PRUNE 0.01001f
#define CAND_CAP 192
#define OUTC    (CC + 3)    // 67

#define HIST_BLOCKS 64                              // 64 x 256 x 4 points
#define SC_BLOCKS   64                              // 16 per batch
#define BQ_BLOCKS   ((BB * NPOINT) / 8)             // 1024 blocks, 8 warps each
#define TR_TILES    ((NN / 32) * (CC / 32) * BB)    // 4096 tiles

// scratch (static device globals; zero-initialized at module load).
// g_counts is re-zeroed inside bq blocks each run so replays start clean.
__device__ int    g_counts  [BB * NCELLS];
__device__ int    g_starts  [BB * NCELLS];         // exclusive scan; starts[c+1] = end of c
__device__ int    g_cellrank[BB * NN];             // (cell<<20)|rank
__device__ float4 g_pts  [BB * NN];                // cell-ordered {x,y,z,bitcast(pid)}
__device__ int    g_idx  [BB * NPOINT * NSAMPLE];  // plain pid per sample
__device__ float  g_ft   [BB * NN * CC];           // features transposed [B][N][C]

// ---------------------------------------------------------------- K1: histogram (+rank)
__global__ void __launch_bounds__(256) hist_kernel(const float* __restrict__ xyz)
{
    int t0 = blockIdx.x * 256 + threadIdx.x;
#pragma unroll
    for (int k = 0; k < 4; k++) {
        int i = t0 + k * (HIST_BLOCKS * 256);
        float x = xyz[i * 3 + 0];
        float y = xyz[i * 3 + 1];
        float z = xyz[i * 3 + 2];
        int cx = (int)(x * 10.0f); cx = cx < 0 ? 0 : (cx > GRID - 1 ? GRID - 1 : cx);
        int cy = (int)(y * 10.0f); cy = cy < 0 ? 0 : (cy > GRID - 1 ? GRID - 1 : cy);
        int cz = (int)(z * 10.0f); cz = cz < 0 ? 0 : (cz > GRID - 1 ? GRID - 1 : cz);
        int cell = (cz * GRID + cy) * GRID + cx;
        int b = i / NN;
        int rank = atomicAdd(&g_counts[b * NCELLS + cell], 1);
        g_cellrank[i] = (cell << 20) | rank;
    }
}

// ---------------------------------------------------------------- K2: scan (redundant per block) + scatter
__global__ void __launch_bounds__(256) scan_scatter_kernel(const float* __restrict__ xyz)
{
    __shared__ int starts_s[NCELLS];
    __shared__ int wsum[8];

    int bb = blockIdx.x;          // 0..63
    int b  = bb >> 4;             // batch
    int t  = threadIdx.x;
    int lane = t & 31, wid = t >> 5;

    int base = t * 4;
    const int* cnt = g_counts + b * NCELLS;
    int a0 = cnt[base + 0], a1 = cnt[base + 1], a2 = cnt[base + 2], a3 = cnt[base + 3];
    int s = a0 + a1 + a2 + a3;
    int incl = s;
#pragma unroll
    for (int o = 1; o < 32; o <<= 1) {
        int y = __shfl_up_sync(0xffffffffu, incl, o);
        if (lane >= o) incl += y;
    }
    if (lane == 31) wsum[wid] = incl;
    __syncthreads();
    if (wid == 0 && lane < 8) {
        int w = wsum[lane];
        int wi = w;
#pragma unroll
        for (int o = 1; o < 8; o <<= 1) {
            int y = __shfl_up_sync(0x000000ffu, wi, o);
            if (lane >= o) wi += y;
        }
        wsum[lane] = wi - w;
    }
    __syncthreads();
    int excl = incl - s + wsum[wid];
    starts_s[base + 0] = excl;
    starts_s[base + 1] = excl + a0;
    starts_s[base + 2] = excl + a0 + a1;
    starts_s[base + 3] = excl + a0 + a1 + a2;
    __syncthreads();

    if ((bb & 15) == 0) {
#pragma unroll
        for (int k = 0; k < 4; k++)
            g_starts[b * NCELLS + base + k] = starts_s[base + k];
    }

    int chunk = (bb & 15) * 1024;
#pragma unroll
    for (int k = 0; k < 4; k++) {
        int i = chunk + t + k * 256;
        int gi = b * NN + i;
        int cr = g_cellrank[gi];
        int cell = cr >> 20;
        int rank = cr & 0xfffff;
        int slot = starts_s[cell] + rank;
        const float* p = xyz + (size_t)gi * 3;
        g_pts[b * NN + slot] = make_float4(p[0], p[1], p[2], __int_as_float(i));
    }
}

// ---------------------------------------------------------------- register bitonic helpers
__device__ __forceinline__ int bsort32(int v, int lane) {
#pragma unroll
    for (int k = 2; k <= 32; k <<= 1) {
#pragma unroll
        for (int j = k >> 1; j > 0; j >>= 1) {
            int p = __shfl_xor_sync(0xffffffffu, v, j);
            bool keep_min = ((lane & j) == 0) == ((lane & k) == 0);
            v = keep_min ? min(v, p) : max(v, p);
        }
    }
    return v;   // ascending across lanes
}

// ---------------------------------------------------------------- K3: ball query (warp/query, writes xyz channels) ∥ transpose
__global__ void __launch_bounds__(256) bq_tr_kernel(
    const float* __restrict__ new_xyz, const float* __restrict__ feat,
    const float* __restrict__ xyz, float* __restrict__ out)
{
    if (blockIdx.x >= BQ_BLOCKS) {
        __shared__ float tile[32][33];
        int tb  = blockIdx.x - BQ_BLOCKS;
        int b   = tb / ((NN / 32) * (CC / 32));
        int rem = tb % ((NN / 32) * (CC / 32));
        int n0  = (rem % (NN / 32)) * 32;
        int c0  = (rem / (NN / 32)) * 32;
        int t   = threadIdx.x;

        int c  = t >> 3;          // 0..31
        int nq = t & 7;           // 0..7
        float4 v = *(const float4*)(feat + ((size_t)(b * CC + c0 + c)) * NN + n0 + 4 * nq);
        tile[4 * nq + 0][c] = v.x;
        tile[4 * nq + 1][c] = v.y;
        tile[4 * nq + 2][c] = v.z;
        tile[4 * nq + 3][c] = v.w;
        __syncthreads();

        int n  = t >> 3;
        int cq = t & 7;
        float4 w = make_float4(tile[n][4 * cq + 0], tile[n][4 * cq + 1],
                               tile[n][4 * cq + 2], tile[n][4 * cq + 3]);
        *(float4*)(g_ft + ((size_t)(b * NN + n0 + n)) * CC + c0 + 4 * cq) = w;
        return;
    }

    // re-zero g_counts for the next run (scan_scatter already consumed it)
    if (blockIdx.x < 16)
        g_counts[blockIdx.x * 256 + threadIdx.x] = 0;

    __shared__ int buf_s[8][CAND_CAP];
    int warp = threadIdx.x >> 5;
    int lane = threadIdx.x & 31;
    int qid  = blockIdx.x * 8 + warp;
    int b = qid / NPOINT;
    int p = qid % NPOINT;

    float qx = new_xyz[qid * 3 + 0];
    float qy = new_xyz[qid * 3 + 1];
    float qz = new_xyz[qid * 3 + 2];
    int cy = (int)(qy * 10.0f); cy = cy < 0 ? 0 : (cy > GRID - 1 ? GRID - 1 : cy);
    int cz = (int)(qz * 10.0f); cz = cz < 0 ? 0 : (cz > GRID - 1 ? GRID - 1 : cz);

    const float4* pts = g_pts + b * NN;
    const int* starts = g_starts + b * NCELLS;

    // ---- per-lane span precompute: lanes 0..8 each own one (z,y) span.
    // Both starts[] loads for all spans issue in parallel (2 LDG total).
    int my_s0 = 0, my_len = 0;
    {
        int zi = lane / 3, yi = lane - zi * 3;       // lane < 9
        int zc = cz - 1 + zi;
        int yc = cy - 1 + yi;
        bool ok = (lane < 9) && (zc >= 0) && (zc < GRID) && (yc >= 0) && (yc < GRID);
        float dz = (zc < cz) ? (qz - (zc + 1) * 0.1f) : ((zc > cz) ? (zc * 0.1f - qz) : 0.0f);
        float dyv = (yc < cy) ? (qy - (yc + 1) * 0.1f) : ((yc > cy) ? (yc * 0.1f - qy) : 0.0f);
        float rem2 = R2PRUNE - dz * dz - dyv * dyv;
        ok = ok && (rem2 > 0.0f);
        if (ok) {
            float rx = sqrtf(rem2);
            int xlo = (int)((qx - rx) * 10.0f); xlo = xlo < 0 ? 0 : (xlo > GRID - 1 ? GRID - 1 : xlo);
            int xhi = (int)((qx + rx) * 10.0f); xhi = xhi < 0 ? 0 : (xhi > GRID - 1 ? GRID - 1 : xhi);
            int bse = (zc * GRID + yc) * GRID;
            int s0 = starts[bse + xlo];
            int e  = starts[bse + xhi + 1];
            my_s0 = s0;
            my_len = e - s0;
        }
    }

    int* buf = buf_s[warp];
    int cnt = 0;

#pragma unroll
    for (int sp = 0; sp < 9; sp++) {
        int len = __shfl_sync(0xffffffffu, my_len, sp);
        if (len == 0) continue;
        int s0 = __shfl_sync(0xffffffffu, my_s0, sp);
        for (int j0 = 0; j0 < len; j0 += 32) {
            int j = j0 + lane;
            bool valid = false;
            int packed = 0;
            if (j < len) {
                float4 pt = pts[s0 + j];
                float ddx = qx - pt.x;
                float ddy = qy - pt.y;
                float ddz = qz - pt.z;
                valid = (ddx * ddx + ddy * ddy + ddz * ddz) < R2;
                packed = (__float_as_int(pt.w) << 14) | (s0 + j);   // (pid<<14)|slot
            }
            unsigned m = __ballot_sync(0xffffffffu, valid);
            int off = __popc(m & ((1u << lane) - 1));
            if (valid && (cnt + off) < CAND_CAP) buf[cnt + off] = packed;
            cnt += __popc(m);
            if (cnt > CAND_CAP) cnt = CAND_CAP;
        }
    }
    __syncwarp();

    // top-32 smallest packed (== smallest pid) via register bitonic sort+merge
    int res = (lane < cnt) ? buf[lane] : 0x7fffffff;
    res = bsort32(res, lane);
    int nchunks = (cnt + 31) >> 5;
    for (int c = 1; c < nchunks; c++) {
        int idx = c * 32 + lane;
        int v = (idx < cnt) ? buf[idx] : 0x7fffffff;
        v = bsort32(v, lane);
        int vr = __shfl_sync(0xffffffffu, v, 31 - lane);
        res = min(res, vr);
#pragma unroll
        for (int j = 16; j > 0; j >>= 1) {
            int pp = __shfl_xor_sync(0xffffffffu, res, j);
            res = ((lane & j) == 0) ? min(res, pp) : max(res, pp);
        }
    }
    int first = __shfl_sync(0xffffffffu, res, 0);
    int eff = (lane < cnt) ? res : first;

    float px, py, pz;
    int pid;
    if (cnt == 0) {
        pid = 0;
        px = xyz[(size_t)b * NN * 3 + 0];   // broadcast
        py = xyz[(size_t)b * NN * 3 + 1];
        pz = xyz[(size_t)b * NN * 3 + 2];
    } else {
        pid = eff >> 14;
        float4 pt = pts[eff & 0x3fff];      // clustered slots: few sectors
        px = pt.x; py = pt.y; pz = pt.z;
    }

    // xyz output channels: coalesced 128B streaming stores
    size_t ob = (((size_t)b * OUTC) * NPOINT + p) * NSAMPLE + lane;
    __stcs(&out[ob],                                px - qx);
    __stcs(&out[ob + (size_t)NPOINT * NSAMPLE],     py - qy);
    __stcs(&out[ob + 2 * (size_t)NPOINT * NSAMPLE], pz - qz);

    g_idx[qid * NSAMPLE + lane] = pid;
}

// ---------------------------------------------------------------- K4: grouping (features only, 2 queries/block)
__global__ void __launch_bounds__(256) group_kernel(float* __restrict__ out)
{
    __shared__ __align__(16) float T[2][NSAMPLE][OUTC];   // stride 67

    int t    = threadIdx.x;
    int ql   = t >> 7;                 // 0/1: query within block
    int tl   = t & 127;
    int lane = t & 31;
    int w    = tl >> 5;                // warp within query 0..3
    int qid  = blockIdx.x * 2 + ql;
    int b = qid / NPOINT;
    int p = qid % NPOINT;

    // per-warp coalesced idx load; sample s pid lives in lane s
    int v = g_idx[qid * NSAMPLE + lane];

    // rows for this warp's samples (w*8..w*8+7) via shfl; batch loads for MLP
    int rows[8];
#pragma unroll
    for (int j = 0; j < 8; j++)
        rows[j] = __shfl_sync(0xffffffffu, v, w * 8 + j);
    float2 vals[8];
#pragma unroll
    for (int j = 0; j < 8; j++)
        vals[j] = ((const float2*)(g_ft + ((size_t)(b * NN + rows[j])) * CC))[lane];

#pragma unroll
    for (int j = 0; j < 8; j++) {
        int s = w * 8 + j;                 // parity(s) == parity(j)
        if ((j & 1) == 0) {
            *(float2*)&T[ql][s][2 * lane] = vals[j];
        } else {
            T[ql][s][2 * lane + 0] = vals[j].x;
            T[ql][s][2 * lane + 1] = vals[j].y;
        }
    }
    __syncthreads();

    // feature output: float4 along sample dim; per instr each warp covers
    // 4 channels x 8 sample-quarters = 4 contiguous 128B rows (fully coalesced)
    float4* out4 = (float4*)(out + (((size_t)b * OUTC + 3) * NPOINT + p) * NSAMPLE);
#pragma unroll
    for (int k = 0; k < 4; k++) {
        int f  = tl + 128 * k;
        int c  = f >> 3;
        int sq = f & 7;
        float4 wv;
        wv.x = T[ql][4 * sq + 0][c];
        wv.y = T[ql][4 * sq + 1][c];
        wv.z = T[ql][4 * sq + 2][c];
        wv.w = T[ql][4 * sq + 3][c];
        __stcs(&out4[(size_t)c * (NPOINT * NSAMPLE / 4) + sq], wv);
    }
}

// ---------------------------------------------------------------- launch
extern "C" void kernel_launch(void* const* d_in, const int* in_sizes, int n_in,
                              void* d_out, int out_size)
{
    const float* xyz     = (const float*)d_in[0];
    const float* new_xyz = (const float*)d_in[1];
    const float* feat    = (const float*)d_in[2];
    float* out = (float*)d_out;

    hist_kernel<<<HIST_BLOCKS, 256>>>(xyz);
    scan_scatter_kernel<<<SC_BLOCKS, 256>>>(xyz);
    bq_tr_kernel<<<BQ_BLOCKS + TR_TILES, 256>>>(new_xyz, feat, xyz, out);
    group_kernel<<<BB * NPOINT / 2, 256>>>(out);
}

// round 17
// speedup vs baseline: 1.1633x; 1.0585x over previous
#include <cuda_runtime.h>
#include <stdint.h>

#define BB      4
#define NN      16384
#define NPOINT  2048
#define CC      64
#define NSAMPLE 32
#define GRID    10
#define NCELLS  1024        // 10*10*10 = 1000, padded (pad cells scan to total)
#define R2      0.01f
#define R2PRUNE 0.01001f
#define CAND_CAP 192
#define OUTC    (CC + 3)    // 67

#define HIST_BLOCKS 64                              // 64 x 256 x 4 points
#define SC_BLOCKS   64                              // 16 per batch
#define BQ_BLOCKS   ((BB * NPOINT) / 8)             // 1024 blocks, 8 warps each
#define GR_BLOCKS   ((BB * NPOINT) / 2)             // 4096 group blocks
#define TR_TILES    ((NN / 32) * (CC / 32) * BB)    // 4096 tiles
#define TR_K1       2048
#define TR_K2       (TR_TILES - TR_K1)              // 2048

// scratch (static device globals; zero-initialized at module load).
// g_counts re-zeroed inside bq blocks; g_flag consumed+reset by group blocks.
__device__ int    g_counts  [BB * NCELLS];
__device__ int    g_starts  [BB * NCELLS];         // exclusive scan; starts[c+1] = end of c
__device__ int    g_cellrank[BB * NN];             // (cell<<20)|rank
__device__ float4 g_pts  [BB * NN];                // cell-ordered {x,y,z,bitcast(pid)}
__device__ int    g_idx  [BB * NPOINT * NSAMPLE];  // plain pid per sample
__device__ int    g_flag [BB * NPOINT];            // per-query ready flag
__device__ float  g_ft   [BB * NN * CC];           // features transposed [B][N][C]

// ---------------------------------------------------------------- transpose one 32x32 tile of [B,C,N] -> [B,N,C]
__device__ __forceinline__ void tr_tile(int tb, const float* __restrict__ feat)
{
    __shared__ float tile[32][33];
    int b   = tb / ((NN / 32) * (CC / 32));
    int rem = tb % ((NN / 32) * (CC / 32));
    int n0  = (rem % (NN / 32)) * 32;
    int c0  = (rem / (NN / 32)) * 32;
    int t   = threadIdx.x;

    int c  = t >> 3;          // 0..31
    int nq = t & 7;           // 0..7
    float4 v = *(const float4*)(feat + ((size_t)(b * CC + c0 + c)) * NN + n0 + 4 * nq);
    tile[4 * nq + 0][c] = v.x;
    tile[4 * nq + 1][c] = v.y;
    tile[4 * nq + 2][c] = v.z;
    tile[4 * nq + 3][c] = v.w;
    __syncthreads();

    int n  = t >> 3;
    int cq = t & 7;
    float4 w = make_float4(tile[n][4 * cq + 0], tile[n][4 * cq + 1],
                           tile[n][4 * cq + 2], tile[n][4 * cq + 3]);
    *(float4*)(g_ft + ((size_t)(b * NN + n0 + n)) * CC + c0 + 4 * cq) = w;
}

// ---------------------------------------------------------------- K1: histogram (+rank) ∥ transpose part 1
__global__ void __launch_bounds__(256) hist_kernel(
    const float* __restrict__ xyz, const float* __restrict__ feat)
{
    if (blockIdx.x >= HIST_BLOCKS) {
        tr_tile(blockIdx.x - HIST_BLOCKS, feat);
        return;
    }
    int t0 = blockIdx.x * 256 + threadIdx.x;
#pragma unroll
    for (int k = 0; k < 4; k++) {
        int i = t0 + k * (HIST_BLOCKS * 256);
        float x = xyz[i * 3 + 0];
        float y = xyz[i * 3 + 1];
        float z = xyz[i * 3 + 2];
        int cx = (int)(x * 10.0f); cx = cx < 0 ? 0 : (cx > GRID - 1 ? GRID - 1 : cx);
        int cy = (int)(y * 10.0f); cy = cy < 0 ? 0 : (cy > GRID - 1 ? GRID - 1 : cy);
        int cz = (int)(z * 10.0f); cz = cz < 0 ? 0 : (cz > GRID - 1 ? GRID - 1 : cz);
        int cell = (cz * GRID + cy) * GRID + cx;
        int b = i / NN;
        int rank = atomicAdd(&g_counts[b * NCELLS + cell], 1);
        g_cellrank[i] = (cell << 20) | rank;
    }
}

// ---------------------------------------------------------------- K2: scan + scatter ∥ transpose part 2
__global__ void __launch_bounds__(256) scan_scatter_kernel(
    const float* __restrict__ xyz, const float* __restrict__ feat)
{
    if (blockIdx.x >= SC_BLOCKS) {
        tr_tile(TR_K1 + blockIdx.x - SC_BLOCKS, feat);
        return;
    }

    __shared__ int starts_s[NCELLS];
    __shared__ int wsum[8];

    int bb = blockIdx.x;          // 0..63
    int b  = bb >> 4;             // batch
    int t  = threadIdx.x;
    int lane = t & 31, wid = t >> 5;

    int base = t * 4;
    const int* cnt = g_counts + b * NCELLS;
    int a0 = cnt[base + 0], a1 = cnt[base + 1], a2 = cnt[base + 2], a3 = cnt[base + 3];
    int s = a0 + a1 + a2 + a3;
    int incl = s;
#pragma unroll
    for (int o = 1; o < 32; o <<= 1) {
        int y = __shfl_up_sync(0xffffffffu, incl, o);
        if (lane >= o) incl += y;
    }
    if (lane == 31) wsum[wid] = incl;
    __syncthreads();
    if (wid == 0 && lane < 8) {
        int w = wsum[lane];
        int wi = w;
#pragma unroll
        for (int o = 1; o < 8; o <<= 1) {
            int y = __shfl_up_sync(0x000000ffu, wi, o);
            if (lane >= o) wi += y;
        }
        wsum[lane] = wi - w;
    }
    __syncthreads();
    int excl = incl - s + wsum[wid];
    starts_s[base + 0] = excl;
    starts_s[base + 1] = excl + a0;
    starts_s[base + 2] = excl + a0 + a1;
    starts_s[base + 3] = excl + a0 + a1 + a2;
    __syncthreads();

    if ((bb & 15) == 0) {
#pragma unroll
        for (int k = 0; k < 4; k++)
            g_starts[b * NCELLS + base + k] = starts_s[base + k];
    }

    int chunk = (bb & 15) * 1024;
#pragma unroll
    for (int k = 0; k < 4; k++) {
        int i = chunk + t + k * 256;
        int gi = b * NN + i;
        int cr = g_cellrank[gi];
        int cell = cr >> 20;
        int rank = cr & 0xfffff;
        int slot = starts_s[cell] + rank;
        const float* p = xyz + (size_t)gi * 3;
        g_pts[b * NN + slot] = make_float4(p[0], p[1], p[2], __int_as_float(i));
    }
}

// ---------------------------------------------------------------- register bitonic helpers
__device__ __forceinline__ int bsort32(int v, int lane) {
#pragma unroll
    for (int k = 2; k <= 32; k <<= 1) {
#pragma unroll
        for (int j = k >> 1; j > 0; j >>= 1) {
            int p = __shfl_xor_sync(0xffffffffu, v, j);
            bool keep_min = ((lane & j) == 0) == ((lane & k) == 0);
            v = keep_min ? min(v, p) : max(v, p);
        }
    }
    return v;   // ascending across lanes
}

// ---------------------------------------------------------------- K3: fused bq (blocks 0..1023) + group (spin-wait, blocks 1024..)
__global__ void __launch_bounds__(256) bq_group_kernel(
    const float* __restrict__ new_xyz, const float* __restrict__ xyz,
    float* __restrict__ out)
{
    __shared__ __align__(16) float smem_raw[2 * NSAMPLE * OUTC];   // 17152 B, reused

    if (blockIdx.x < BQ_BLOCKS) {
        // ================= ball query =================
        // re-zero g_counts for the next run (scan_scatter already consumed it)
        if (blockIdx.x < 16)
            g_counts[blockIdx.x * 256 + threadIdx.x] = 0;

        int warp = threadIdx.x >> 5;
        int lane = threadIdx.x & 31;
        int qid  = blockIdx.x * 8 + warp;
        int b = qid / NPOINT;
        int p = qid % NPOINT;
        int* buf = (int*)smem_raw + warp * CAND_CAP;

        float qx = new_xyz[qid * 3 + 0];
        float qy = new_xyz[qid * 3 + 1];
        float qz = new_xyz[qid * 3 + 2];
        int cy = (int)(qy * 10.0f); cy = cy < 0 ? 0 : (cy > GRID - 1 ? GRID - 1 : cy);
        int cz = (int)(qz * 10.0f); cz = cz < 0 ? 0 : (cz > GRID - 1 ? GRID - 1 : cz);

        const float4* pts = g_pts + b * NN;
        const int* starts = g_starts + b * NCELLS;

        // per-lane span precompute (lanes 0..8), 2 parallel LDG total
        int my_s0 = 0, my_len = 0;
        {
            int zi = lane / 3, yi = lane - zi * 3;
            int zc = cz - 1 + zi;
            int yc = cy - 1 + yi;
            bool ok = (lane < 9) && (zc >= 0) && (zc < GRID) && (yc >= 0) && (yc < GRID);
            float dz = (zc < cz) ? (qz - (zc + 1) * 0.1f) : ((zc > cz) ? (zc * 0.1f - qz) : 0.0f);
            float dyv = (yc < cy) ? (qy - (yc + 1) * 0.1f) : ((yc > cy) ? (yc * 0.1f - qy) : 0.0f);
            float rem2 = R2PRUNE - dz * dz - dyv * dyv;
            ok = ok && (rem2 > 0.0f);
            if (ok) {
                float rx = sqrtf(rem2);
                int xlo = (int)((qx - rx) * 10.0f); xlo = xlo < 0 ? 0 : (xlo > GRID - 1 ? GRID - 1 : xlo);
                int xhi = (int)((qx + rx) * 10.0f); xhi = xhi < 0 ? 0 : (xhi > GRID - 1 ? GRID - 1 : xhi);
                int bse = (zc * GRID + yc) * GRID;
                int s0 = starts[bse + xlo];
                int e  = starts[bse + xhi + 1];
                my_s0 = s0;
                my_len = e - s0;
            }
        }

        int cnt = 0;
#pragma unroll
        for (int sp = 0; sp < 9; sp++) {
            int len = __shfl_sync(0xffffffffu, my_len, sp);
            if (len == 0) continue;
            int s0 = __shfl_sync(0xffffffffu, my_s0, sp);
            for (int j0 = 0; j0 < len; j0 += 32) {
                int j = j0 + lane;
                bool valid = false;
                int packed = 0;
                if (j < len) {
                    float4 pt = pts[s0 + j];
                    float ddx = qx - pt.x;
                    float ddy = qy - pt.y;
                    float ddz = qz - pt.z;
                    valid = (ddx * ddx + ddy * ddy + ddz * ddz) < R2;
                    packed = (__float_as_int(pt.w) << 14) | (s0 + j);   // (pid<<14)|slot
                }
                unsigned m = __ballot_sync(0xffffffffu, valid);
                int off = __popc(m & ((1u << lane) - 1));
                if (valid && (cnt + off) < CAND_CAP) buf[cnt + off] = packed;
                cnt += __popc(m);
                if (cnt > CAND_CAP) cnt = CAND_CAP;
            }
        }
        __syncwarp();

        int res = (lane < cnt) ? buf[lane] : 0x7fffffff;
        res = bsort32(res, lane);
        int nchunks = (cnt + 31) >> 5;
        for (int c = 1; c < nchunks; c++) {
            int idx = c * 32 + lane;
            int v = (idx < cnt) ? buf[idx] : 0x7fffffff;
            v = bsort32(v, lane);
            int vr = __shfl_sync(0xffffffffu, v, 31 - lane);
            res = min(res, vr);
#pragma unroll
            for (int j = 16; j > 0; j >>= 1) {
                int pp = __shfl_xor_sync(0xffffffffu, res, j);
                res = ((lane & j) == 0) ? min(res, pp) : max(res, pp);
            }
        }
        int first = __shfl_sync(0xffffffffu, res, 0);
        int eff = (lane < cnt) ? res : first;

        float px, py, pz;
        int pid;
        if (cnt == 0) {
            pid = 0;
            px = xyz[(size_t)b * NN * 3 + 0];
            py = xyz[(size_t)b * NN * 3 + 1];
            pz = xyz[(size_t)b * NN * 3 + 2];
        } else {
            pid = eff >> 14;
            float4 pt = pts[eff & 0x3fff];
            px = pt.x; py = pt.y; pz = pt.z;
        }

        // xyz output channels: coalesced 128B streaming stores
        size_t ob = (((size_t)b * OUTC) * NPOINT + p) * NSAMPLE + lane;
        __stcs(&out[ob],                                px - qx);
        __stcs(&out[ob + (size_t)NPOINT * NSAMPLE],     py - qy);
        __stcs(&out[ob + 2 * (size_t)NPOINT * NSAMPLE], pz - qz);

        g_idx[qid * NSAMPLE + lane] = pid;

        // publish: all lanes fence, converge, lane 0 sets flag
        __threadfence();
        __syncwarp();
        if (lane == 0) atomicExch(&g_flag[qid], 1);
        return;
    }

    // ================= group (spin-wait) =================
    float (*T)[NSAMPLE][OUTC] = (float (*)[NSAMPLE][OUTC])smem_raw;
    int gb   = blockIdx.x - BQ_BLOCKS;
    int t    = threadIdx.x;
    int ql   = t >> 7;
    int tl   = t & 127;
    int lane = t & 31;
    int w    = tl >> 5;
    int qid  = gb * 2 + ql;
    int b = qid / NPOINT;
    int p = qid % NPOINT;

    // wait for this block's two queries
    if (t == 0 || t == 128) {
        while (atomicAdd(&g_flag[qid], 0) == 0) {}
        __threadfence();
    }
    __syncthreads();

    // per-warp coalesced idx load; sample s pid lives in lane s
    int v = g_idx[qid * NSAMPLE + lane];

    int rows[8];
#pragma unroll
    for (int j = 0; j < 8; j++)
        rows[j] = __shfl_sync(0xffffffffu, v, w * 8 + j);
    float2 vals[8];
#pragma unroll
    for (int j = 0; j < 8; j++)
        vals[j] = ((const float2*)(g_ft + ((size_t)(b * NN + rows[j])) * CC))[lane];

#pragma unroll
    for (int j = 0; j < 8; j++) {
        int s = w * 8 + j;                 // parity(s) == parity(j)
        if ((j & 1) == 0) {
            *(float2*)&T[ql][s][2 * lane] = vals[j];
        } else {
            T[ql][s][2 * lane + 0] = vals[j].x;
            T[ql][s][2 * lane + 1] = vals[j].y;
        }
    }
    __syncthreads();

    // reset flags for next replay (g_idx reads are before the barrier above)
    if (t == 0 || t == 128) g_flag[qid] = 0;

    // feature output: float4 along sample dim; fully coalesced 128B rows
    float4* out4 = (float4*)(out + (((size_t)b * OUTC + 3) * NPOINT + p) * NSAMPLE);
#pragma unroll
    for (int k = 0; k < 4; k++) {
        int f  = tl + 128 * k;
        int c  = f >> 3;
        int sq = f & 7;
        float4 wv;
        wv.x = T[ql][4 * sq + 0][c];
        wv.y = T[ql][4 * sq + 1][c];
        wv.z = T[ql][4 * sq + 2][c];
        wv.w = T[ql][4 * sq + 3][c];
        __stcs(&out4[(size_t)c * (NPOINT * NSAMPLE / 4) + sq], wv);
    }
}

// ---------------------------------------------------------------- launch
extern "C" void kernel_launch(void* const* d_in, const int* in_sizes, int n_in,
                              void* d_out, int out_size)
{
    const float* xyz     = (const float*)d_in[0];
    const float* new_xyz = (const float*)d_in[1];
    const float* feat    = (const float*)d_in[2];
    float* out = (float*)d_out;

    hist_kernel<<<HIST_BLOCKS + TR_K1, 256>>>(xyz, feat);
    scan_scatter_kernel<<<SC_BLOCKS + TR_K2, 256>>>(xyz, feat);
    bq_group_kernel<<<BQ_BLOCKS + GR_BLOCKS, 256>>>(new_xyz, xyz, out);
}